// round 2
// baseline (speedup 1.0000x reference)
#include <cuda_runtime.h>
#include <cstdint>

// Problem dims (fixed by the dataset)
#define MD 8192   // B*S = 4*2048
#define ND 4096   // D_OUT
#define KD 4096   // D_IN
#define QBLOCK 64

static __constant__ float c_nf4[16] = {
    -1.0f, -0.6961928009986877f, -0.5250730514526367f, -0.39491748809814453f,
    -0.28444138169288635f, -0.18477343022823334f, -0.09105003625154495f, 0.0f,
    0.07958029955625534f, 0.16093020141124725f, 0.24611230194568634f,
    0.33791524171829224f, 0.44070982933044434f, 0.5626170039176941f,
    0.6848514676094055f, 1.0f
};

// Scratch: dequantized weights (fp32) + bias. Static device globals (allowed).
__device__ float g_W[(size_t)ND * KD];   // 64 MB
__device__ float g_bias[ND];

// ---------------------------------------------------------------------------
// Kernel 1: dequantize W codes -> fp32 weights. 4 codes per thread (int4/float4).
// absmax block index for flat element e is e/64; for float4 index i it's i/16.
// ---------------------------------------------------------------------------
__global__ void k_dequant_w(const int4* __restrict__ codes,
                            const float* __restrict__ absmax) {
    int i = blockIdx.x * blockDim.x + threadIdx.x;   // [0, ND*KD/4)
    int4 c = codes[i];
    float am = __ldg(&absmax[i >> 4]);
    float4 v;
    v.x = c_nf4[c.x] * am;
    v.y = c_nf4[c.y] * am;
    v.z = c_nf4[c.z] * am;
    v.w = c_nf4[c.w] * am;
    reinterpret_cast<float4*>(g_W)[i] = v;
}

__global__ void k_dequant_b(const int* __restrict__ codes,
                            const float* __restrict__ absmax) {
    int i = blockIdx.x * blockDim.x + threadIdx.x;
    if (i < ND) g_bias[i] = c_nf4[codes[i]] * absmax[i >> 6];
}

// ---------------------------------------------------------------------------
// Kernel 2: fp32 SIMT GEMM, C[M,N] = A[M,K] * W[N,K]^T + bias.
// 128x128 block tile, 8x8 per-thread register tile, BK=16.
// Smem stored k-major transposed (As[k][m], Bs[k][n]) with stride 132 so that
// float4 smem reads stay 16B-aligned (132*4 = 528 = 33*16) and the transposed
// float4->4xSTS scatter is only 2-way bank conflicted.
// ---------------------------------------------------------------------------
#define BM 128
#define BN 128
#define BK 16
#define SPAD 132

__global__ __launch_bounds__(256, 2)
void k_gemm(const float* __restrict__ A, float* __restrict__ C) {
    __shared__ float As[BK][SPAD];
    __shared__ float Bs[BK][SPAD];

    const int tid = threadIdx.x;
    const int tx = tid & 15;        // n-tile within block (0..15)
    const int ty = tid >> 4;        // m-tile within block (0..15)
    const int m0 = blockIdx.y * BM;
    const int n0 = blockIdx.x * BN;

    float acc[8][8];
#pragma unroll
    for (int i = 0; i < 8; i++)
#pragma unroll
        for (int j = 0; j < 8; j++) acc[i][j] = 0.0f;

    const float* __restrict__ Bg = g_W;

    for (int k0 = 0; k0 < KD; k0 += BK) {
        // Cooperative tile load: 512 float4 per operand, 2 per thread.
#pragma unroll
        for (int r = 0; r < 2; r++) {
            int j  = tid + r * 256;
            int m  = j >> 2;             // 0..127
            int k4 = (j & 3) << 2;       // 0,4,8,12
            float4 a = *reinterpret_cast<const float4*>(
                A + (size_t)(m0 + m) * KD + k0 + k4);
            As[k4 + 0][m] = a.x; As[k4 + 1][m] = a.y;
            As[k4 + 2][m] = a.z; As[k4 + 3][m] = a.w;
            float4 b = *reinterpret_cast<const float4*>(
                Bg + (size_t)(n0 + m) * KD + k0 + k4);
            Bs[k4 + 0][m] = b.x; Bs[k4 + 1][m] = b.y;
            Bs[k4 + 2][m] = b.z; Bs[k4 + 3][m] = b.w;
        }
        __syncthreads();

#pragma unroll
        for (int k = 0; k < BK; k++) {
            float af[8], bf[8];
            *reinterpret_cast<float4*>(&af[0]) =
                *reinterpret_cast<const float4*>(&As[k][ty * 8]);
            *reinterpret_cast<float4*>(&af[4]) =
                *reinterpret_cast<const float4*>(&As[k][ty * 8 + 4]);
            *reinterpret_cast<float4*>(&bf[0]) =
                *reinterpret_cast<const float4*>(&Bs[k][tx * 8]);
            *reinterpret_cast<float4*>(&bf[4]) =
                *reinterpret_cast<const float4*>(&Bs[k][tx * 8 + 4]);
#pragma unroll
            for (int i = 0; i < 8; i++)
#pragma unroll
                for (int j = 0; j < 8; j++)
                    acc[i][j] = fmaf(af[i], bf[j], acc[i][j]);
        }
        __syncthreads();
    }

    // Epilogue: add bias, vectorized stores.
    float bias[8];
#pragma unroll
    for (int j = 0; j < 8; j++) bias[j] = __ldg(&g_bias[n0 + tx * 8 + j]);

#pragma unroll
    for (int i = 0; i < 8; i++) {
        int row = m0 + ty * 8 + i;
        float* outp = C + (size_t)row * ND + n0 + tx * 8;
#pragma unroll
        for (int j = 0; j < 8; j += 4) {
            float4 v;
            v.x = acc[i][j + 0] + bias[j + 0];
            v.y = acc[i][j + 1] + bias[j + 1];
            v.z = acc[i][j + 2] + bias[j + 2];
            v.w = acc[i][j + 3] + bias[j + 3];
            *reinterpret_cast<float4*>(outp + j) = v;
        }
    }
}

// ---------------------------------------------------------------------------
// Launch. Input order per metadata: x, w_codes, w_absmax, b_codes, b_absmax.
// ---------------------------------------------------------------------------
extern "C" void kernel_launch(void* const* d_in, const int* in_sizes, int n_in,
                              void* d_out, int out_size) {
    const float* x        = (const float*)d_in[0];   // [8192, 4096]
    const int*   w_codes  = (const int*)  d_in[1];   // [4096, 4096]
    const float* w_absmax = (const float*)d_in[2];   // [262144]
    const int*   b_codes  = (const int*)  d_in[3];   // [4096]
    const float* b_absmax = (const float*)d_in[4];   // [64]
    float*       out      = (float*)d_out;           // [8192, 4096]

    (void)in_sizes; (void)n_in; (void)out_size;

    // Dequantize W (4 codes/thread) and bias.
    int n_vec4 = (ND * KD) / 4;                      // 4,194,304
    k_dequant_w<<<n_vec4 / 256, 256>>>((const int4*)w_codes, w_absmax);
    k_dequant_b<<<ND / 256, 256>>>(b_codes, b_absmax);

    // GEMM
    dim3 grid(ND / BN, MD / BM);   // (32, 64)
    k_gemm<<<grid, 256>>>(x, out);
}

// round 5
// speedup vs baseline: 6.8307x; 6.8307x over previous
#include <cuda_runtime.h>
#include <cuda_fp16.h>
#include <cstdint>
#include <cstddef>

// Problem dims (fixed)
#define MD 8192
#define ND 4096
#define KD 4096

// GEMM tiling (sm80-class mma.sync pipeline)
#define BM 128
#define BN 256
#define BK 32
#define STAGES 3
#define NT (KD / BK)                     // 128
#define A_STAGE_BYTES (BM * 64)          // 128 rows * 32 fp16 = 8 KB
#define B_STAGE_BYTES (BN * 64)          // 16 KB
#define STAGE_BYTES (A_STAGE_BYTES + B_STAGE_BYTES)
#define DYN_SMEM (STAGES * STAGE_BYTES)  // 73728

static __constant__ float c_nf4[16] = {
    -1.0f, -0.6961928009986877f, -0.5250730514526367f, -0.39491748809814453f,
    -0.28444138169288635f, -0.18477343022823334f, -0.09105003625154495f, 0.0f,
    0.07958029955625534f, 0.16093020141124725f, 0.24611230194568634f,
    0.33791524171829224f, 0.44070982933044434f, 0.5626170039176941f,
    0.6848514676094055f, 1.0f
};

// Scratch (static device globals are the sanctioned path)
__device__ __half g_Wh[(size_t)ND * KD];   // 32 MB fp16 weights
__device__ __half g_Xh[(size_t)MD * KD];   // 64 MB fp16 activations
__device__ float  g_bias[ND];

// Pack 8 halves (as 4 __half2) into a uint4 for one 16B store.
union H8 {
    uint4 u;
    __half2 h[4];
};

// ---------------------------------------------------------------------------
// Prep kernels
// ---------------------------------------------------------------------------
__global__ void k_dequant_w(const int4* __restrict__ codes,
                            const float* __restrict__ absmax) {
    int i = blockIdx.x * blockDim.x + threadIdx.x;     // [0, ND*KD/8)
    int4 c0 = codes[2 * i];
    int4 c1 = codes[2 * i + 1];
    float am = __ldg(&absmax[i >> 3]);                 // 8 codes/thread, 64/8
    H8 v;
    v.h[0] = __floats2half2_rn(c_nf4[c0.x] * am, c_nf4[c0.y] * am);
    v.h[1] = __floats2half2_rn(c_nf4[c0.z] * am, c_nf4[c0.w] * am);
    v.h[2] = __floats2half2_rn(c_nf4[c1.x] * am, c_nf4[c1.y] * am);
    v.h[3] = __floats2half2_rn(c_nf4[c1.z] * am, c_nf4[c1.w] * am);
    reinterpret_cast<uint4*>(g_Wh)[i] = v.u;
}

__global__ void k_convert_x(const float4* __restrict__ x) {
    int i = blockIdx.x * blockDim.x + threadIdx.x;     // [0, MD*KD/8)
    float4 a = x[2 * i];
    float4 b = x[2 * i + 1];
    H8 v;
    v.h[0] = __floats2half2_rn(a.x, a.y);
    v.h[1] = __floats2half2_rn(a.z, a.w);
    v.h[2] = __floats2half2_rn(b.x, b.y);
    v.h[3] = __floats2half2_rn(b.z, b.w);
    reinterpret_cast<uint4*>(g_Xh)[i] = v.u;
}

__global__ void k_dequant_b(const int* __restrict__ codes,
                            const float* __restrict__ absmax) {
    int i = blockIdx.x * blockDim.x + threadIdx.x;
    if (i < ND) g_bias[i] = c_nf4[codes[i]] * absmax[i >> 6];
}

// ---------------------------------------------------------------------------
// PTX helpers (all baseline sm_80+ — no 'a'-gated features)
// ---------------------------------------------------------------------------
__device__ __forceinline__ uint32_t smem_u32(const void* p) {
    uint32_t a;
    asm("{ .reg .u64 t; cvta.to.shared.u64 t, %1; cvt.u32.u64 %0, t; }"
        : "=r"(a) : "l"(p));
    return a;
}

#define CP_ASYNC16(saddr, gptr) \
    asm volatile("cp.async.cg.shared.global [%0], [%1], 16;" \
                 :: "r"(saddr), "l"(gptr))

#define CP_COMMIT() asm volatile("cp.async.commit_group;" ::: "memory")
#define CP_WAIT(n)  asm volatile("cp.async.wait_group %0;" :: "n"(n) : "memory")

#define LDSM4(r0, r1, r2, r3, addr) \
    asm volatile("ldmatrix.sync.aligned.m8n8.x4.shared.b16 {%0,%1,%2,%3}, [%4];" \
                 : "=r"(r0), "=r"(r1), "=r"(r2), "=r"(r3) : "r"(addr))

#define MMA16816(d, a, b) \
    asm volatile("mma.sync.aligned.m16n8k16.row.col.f32.f16.f16.f32 " \
                 "{%0,%1,%2,%3}, {%4,%5,%6,%7}, {%8,%9}, {%0,%1,%2,%3};" \
                 : "+f"((d)[0]), "+f"((d)[1]), "+f"((d)[2]), "+f"((d)[3]) \
                 : "r"((a)[0]), "r"((a)[1]), "r"((a)[2]), "r"((a)[3]), \
                   "r"((b)[0]), "r"((b)[1]))

// Smem layout for a [R][32] fp16 tile: row stride 64B, 4 chunks of 16B per
// row, chunk swizzle sc = c ^ ((row>>1)&3)  -> conflict-free ldmatrix + STS.
__device__ __forceinline__ uint32_t tile_off(int row, int c) {
    return (uint32_t)(row * 64 + ((c ^ ((row >> 1) & 3)) << 4));
}

// ---------------------------------------------------------------------------
// GEMM: C[M,N] = Xh[M,K] * Wh[N,K]^T + bias.  256 thr, warp tile 64x64.
// ---------------------------------------------------------------------------
__global__ __launch_bounds__(256)
void k_gemm(float* __restrict__ C) {
    extern __shared__ char dynsmem[];
    const uint32_t sbase = smem_u32(dynsmem);

    const int tid = threadIdx.x;
    const int wid = tid >> 5;
    const int lane = tid & 31;
    const int wm = wid & 1;          // 2 warps along M
    const int wn = wid >> 1;         // 4 warps along N
    const int m0 = blockIdx.y * BM;
    const int n0 = blockIdx.x * BN;

    // ---- cooperative load descriptors (16B chunks) ----
    uint32_t sA[2]; const __half* gA[2];
#pragma unroll
    for (int r = 0; r < 2; r++) {
        int id = tid + r * 256;                 // 0..511
        int row = id >> 2, c = id & 3;
        sA[r] = tile_off(row, c);
        gA[r] = g_Xh + (size_t)(m0 + row) * KD + c * 8;
    }
    uint32_t sB[4]; const __half* gB[4];
#pragma unroll
    for (int r = 0; r < 4; r++) {
        int id = tid + r * 256;                 // 0..1023
        int row = id >> 2, c = id & 3;
        sB[r] = tile_off(row, c);
        gB[r] = g_Wh + (size_t)(n0 + row) * KD + c * 8;
    }

    // ---- ldmatrix lane address components ----
    const int r8 = lane & 7;
    const int grp = lane >> 3;
    const int aCh = grp >> 1;        // k-half selector for A
    const int bCh = grp & 1;         // k-half selector for B
    uint32_t aOff[4], aRs[4];
#pragma unroll
    for (int mt = 0; mt < 4; mt++) {
        int row = wm * 64 + mt * 16 + ((grp & 1) << 3) + r8;
        aOff[mt] = row * 64;
        aRs[mt] = (row >> 1) & 3;
    }
    uint32_t bOff[4], bRs[4];
#pragma unroll
    for (int np = 0; np < 4; np++) {
        int row = wn * 64 + np * 16 + ((grp >> 1) << 3) + r8;
        bOff[np] = row * 64;
        bRs[np] = (row >> 1) & 3;
    }

    float acc[4][8][4];
#pragma unroll
    for (int i = 0; i < 4; i++)
#pragma unroll
        for (int j = 0; j < 8; j++)
#pragma unroll
            for (int q = 0; q < 4; q++) acc[i][j][q] = 0.0f;

    // ---- prologue: fill STAGES-1 stages ----
#pragma unroll
    for (int s = 0; s < STAGES - 1; s++) {
        uint32_t a0 = sbase + s * STAGE_BYTES;
        uint32_t b0 = a0 + A_STAGE_BYTES;
#pragma unroll
        for (int r = 0; r < 2; r++) CP_ASYNC16(a0 + sA[r], gA[r] + s * BK);
#pragma unroll
        for (int r = 0; r < 4; r++) CP_ASYNC16(b0 + sB[r], gB[r] + s * BK);
        CP_COMMIT();
    }
    CP_WAIT(STAGES - 2);
    __syncthreads();

    // ---- mainloop ----
#pragma unroll 1
    for (int kt = 0; kt < NT; kt++) {
        const int nx = kt + STAGES - 1;
        if (nx < NT) {
            uint32_t a0 = sbase + (nx % STAGES) * STAGE_BYTES;
            uint32_t b0 = a0 + A_STAGE_BYTES;
#pragma unroll
            for (int r = 0; r < 2; r++) CP_ASYNC16(a0 + sA[r], gA[r] + nx * BK);
#pragma unroll
            for (int r = 0; r < 4; r++) CP_ASYNC16(b0 + sB[r], gB[r] + nx * BK);
        }
        CP_COMMIT();

        const uint32_t stA = sbase + (kt % STAGES) * STAGE_BYTES;
        const uint32_t stB = stA + A_STAGE_BYTES;

#pragma unroll
        for (int ks = 0; ks < 2; ks++) {
            uint32_t a[4][4], bf[8][2];
#pragma unroll
            for (int mt = 0; mt < 4; mt++) {
                uint32_t addr = stA + aOff[mt] +
                                ((((ks << 1) | aCh) ^ aRs[mt]) << 4);
                LDSM4(a[mt][0], a[mt][1], a[mt][2], a[mt][3], addr);
            }
#pragma unroll
            for (int np = 0; np < 4; np++) {
                uint32_t addr = stB + bOff[np] +
                                ((((ks << 1) | bCh) ^ bRs[np]) << 4);
                LDSM4(bf[2 * np][0], bf[2 * np][1],
                      bf[2 * np + 1][0], bf[2 * np + 1][1], addr);
            }
#pragma unroll
            for (int mt = 0; mt < 4; mt++)
#pragma unroll
                for (int nf = 0; nf < 8; nf++)
                    MMA16816(acc[mt][nf], a[mt], bf[nf]);
        }

        CP_WAIT(STAGES - 2);
        __syncthreads();
    }

    // ---- epilogue ----
    const int qrow = lane >> 2;
    const int qcol = (lane & 3) * 2;
    float2 bias2[8];
#pragma unroll
    for (int nf = 0; nf < 8; nf++) {
        int col = n0 + wn * 64 + nf * 8 + qcol;
        bias2[nf] = *reinterpret_cast<const float2*>(&g_bias[col]);
    }
#pragma unroll
    for (int mt = 0; mt < 4; mt++) {
#pragma unroll
        for (int h = 0; h < 2; h++) {
            int row = m0 + wm * 64 + mt * 16 + qrow + h * 8;
            float* cp = C + (size_t)row * ND + n0 + wn * 64 + qcol;
#pragma unroll
            for (int nf = 0; nf < 8; nf++) {
                float2 v;
                v.x = acc[mt][nf][2 * h + 0] + bias2[nf].x;
                v.y = acc[mt][nf][2 * h + 1] + bias2[nf].y;
                *reinterpret_cast<float2*>(cp + nf * 8) = v;
            }
        }
    }
}

// ---------------------------------------------------------------------------
// Launch. Inputs: x, w_codes, w_absmax, b_codes, b_absmax.
// ---------------------------------------------------------------------------
extern "C" void kernel_launch(void* const* d_in, const int* in_sizes, int n_in,
                              void* d_out, int out_size) {
    const float* x        = (const float*)d_in[0];
    const int*   w_codes  = (const int*)  d_in[1];
    const float* w_absmax = (const float*)d_in[2];
    const int*   b_codes  = (const int*)  d_in[3];
    const float* b_absmax = (const float*)d_in[4];
    float*       out      = (float*)d_out;

    (void)in_sizes; (void)n_in; (void)out_size;

    static bool attr_set = false;
    if (!attr_set) {
        cudaFuncSetAttribute(k_gemm, cudaFuncAttributeMaxDynamicSharedMemorySize,
                             DYN_SMEM);
        attr_set = true;
    }

    k_dequant_w<<<(ND * KD / 8) / 256, 256>>>((const int4*)w_codes, w_absmax);
    k_convert_x<<<(MD * KD / 8) / 256, 256>>>((const float4*)x);
    k_dequant_b<<<ND / 256, 256>>>(b_codes, b_absmax);

    dim3 grid(ND / BN, MD / BM);    // (16, 64)
    k_gemm<<<grid, 256, DYN_SMEM>>>(out);
}

// round 6
// speedup vs baseline: 9.2883x; 1.3598x over previous
#include <cuda_runtime.h>
#include <cuda_fp16.h>
#include <cstdint>
#include <cstddef>

// Problem dims (fixed)
#define MD 8192
#define ND 4096
#define KD 4096

// GEMM tiling
#define BM 128
#define BN 256
#define BK 64                             // 64 fp16 = 128B rows (full SW128)
#define STAGES 3
#define NT (KD / BK)                      // 64
#define A_STAGE_BYTES (BM * 128)          // 16 KB
#define B_STAGE_BYTES (BN * 128)          // 32 KB
#define STAGE_BYTES (A_STAGE_BYTES + B_STAGE_BYTES)   // 48 KB
#define DYN_SMEM (STAGES * STAGE_BYTES)   // 147456

static __constant__ float c_nf4[16] = {
    -1.0f, -0.6961928009986877f, -0.5250730514526367f, -0.39491748809814453f,
    -0.28444138169288635f, -0.18477343022823334f, -0.09105003625154495f, 0.0f,
    0.07958029955625534f, 0.16093020141124725f, 0.24611230194568634f,
    0.33791524171829224f, 0.44070982933044434f, 0.5626170039176941f,
    0.6848514676094055f, 1.0f
};

__device__ __half g_Wh[(size_t)ND * KD];   // 32 MB fp16 weights
__device__ __half g_Xh[(size_t)MD * KD];   // 64 MB fp16 activations
__device__ float  g_bias[ND];

union H8 {
    uint4 u;
    __half2 h[4];
};

// ---------------------------------------------------------------------------
// Prep kernels — 16 elements/thread for MLP=4 (was latency-bound at MLP=2)
// ---------------------------------------------------------------------------
__global__ void k_dequant_w(const int4* __restrict__ codes,
                            const float* __restrict__ absmax) {
    int i = blockIdx.x * blockDim.x + threadIdx.x;     // [0, ND*KD/16)
    int4 c0 = codes[4 * i + 0];
    int4 c1 = codes[4 * i + 1];
    int4 c2 = codes[4 * i + 2];
    int4 c3 = codes[4 * i + 3];
    float am = __ldg(&absmax[i >> 2]);                 // 16 codes/thread, 64/16
    H8 v0, v1;
    v0.h[0] = __floats2half2_rn(c_nf4[c0.x] * am, c_nf4[c0.y] * am);
    v0.h[1] = __floats2half2_rn(c_nf4[c0.z] * am, c_nf4[c0.w] * am);
    v0.h[2] = __floats2half2_rn(c_nf4[c1.x] * am, c_nf4[c1.y] * am);
    v0.h[3] = __floats2half2_rn(c_nf4[c1.z] * am, c_nf4[c1.w] * am);
    v1.h[0] = __floats2half2_rn(c_nf4[c2.x] * am, c_nf4[c2.y] * am);
    v1.h[1] = __floats2half2_rn(c_nf4[c2.z] * am, c_nf4[c2.w] * am);
    v1.h[2] = __floats2half2_rn(c_nf4[c3.x] * am, c_nf4[c3.y] * am);
    v1.h[3] = __floats2half2_rn(c_nf4[c3.z] * am, c_nf4[c3.w] * am);
    reinterpret_cast<uint4*>(g_Wh)[2 * i + 0] = v0.u;
    reinterpret_cast<uint4*>(g_Wh)[2 * i + 1] = v1.u;
}

__global__ void k_convert_x(const float4* __restrict__ x) {
    int i = blockIdx.x * blockDim.x + threadIdx.x;     // [0, MD*KD/16)
    float4 a = x[4 * i + 0];
    float4 b = x[4 * i + 1];
    float4 c = x[4 * i + 2];
    float4 d = x[4 * i + 3];
    H8 v0, v1;
    v0.h[0] = __floats2half2_rn(a.x, a.y);
    v0.h[1] = __floats2half2_rn(a.z, a.w);
    v0.h[2] = __floats2half2_rn(b.x, b.y);
    v0.h[3] = __floats2half2_rn(b.z, b.w);
    v1.h[0] = __floats2half2_rn(c.x, c.y);
    v1.h[1] = __floats2half2_rn(c.z, c.w);
    v1.h[2] = __floats2half2_rn(d.x, d.y);
    v1.h[3] = __floats2half2_rn(d.z, d.w);
    reinterpret_cast<uint4*>(g_Xh)[2 * i + 0] = v0.u;
    reinterpret_cast<uint4*>(g_Xh)[2 * i + 1] = v1.u;
}

__global__ void k_dequant_b(const int* __restrict__ codes,
                            const float* __restrict__ absmax) {
    int i = blockIdx.x * blockDim.x + threadIdx.x;
    if (i < ND) g_bias[i] = c_nf4[codes[i]] * absmax[i >> 6];
}

// ---------------------------------------------------------------------------
// PTX helpers (baseline sm_80+)
// ---------------------------------------------------------------------------
__device__ __forceinline__ uint32_t smem_u32(const void* p) {
    uint32_t a;
    asm("{ .reg .u64 t; cvta.to.shared.u64 t, %1; cvt.u32.u64 %0, t; }"
        : "=r"(a) : "l"(p));
    return a;
}

#define CP_ASYNC16(saddr, gptr) \
    asm volatile("cp.async.cg.shared.global [%0], [%1], 16;" \
                 :: "r"(saddr), "l"(gptr))

#define CP_COMMIT() asm volatile("cp.async.commit_group;" ::: "memory")
#define CP_WAIT(n)  asm volatile("cp.async.wait_group %0;" :: "n"(n) : "memory")

#define LDSM4(r0, r1, r2, r3, addr) \
    asm volatile("ldmatrix.sync.aligned.m8n8.x4.shared.b16 {%0,%1,%2,%3}, [%4];" \
                 : "=r"(r0), "=r"(r1), "=r"(r2), "=r"(r3) : "r"(addr))

#define MMA16816(d, a, b) \
    asm volatile("mma.sync.aligned.m16n8k16.row.col.f32.f16.f16.f32 " \
                 "{%0,%1,%2,%3}, {%4,%5,%6,%7}, {%8,%9}, {%0,%1,%2,%3};" \
                 : "+f"((d)[0]), "+f"((d)[1]), "+f"((d)[2]), "+f"((d)[3]) \
                 : "r"((a)[0]), "r"((a)[1]), "r"((a)[2]), "r"((a)[3]), \
                   "r"((b)[0]), "r"((b)[1]))

// 128B-row SW128 swizzle: 16B chunk index c (0..7), swizzled c ^ (row & 7).
__device__ __forceinline__ uint32_t tile_off(int row, int c) {
    return (uint32_t)(row * 128 + ((c ^ (row & 7)) << 4));
}

// ---------------------------------------------------------------------------
// GEMM: C[M,N] = Xh[M,K] * Wh[N,K]^T + bias.  256 thr, warp tile 64x64.
// Fragment double-buffered: LDSM of ks+1 overlaps MMA of ks.
// ---------------------------------------------------------------------------
__global__ __launch_bounds__(256)
void k_gemm(float* __restrict__ C) {
    extern __shared__ char dynsmem[];
    const uint32_t sbase = smem_u32(dynsmem);

    const int tid = threadIdx.x;
    const int wid = tid >> 5;
    const int lane = tid & 31;
    const int wm = wid & 1;          // 2 warps along M
    const int wn = wid >> 1;         // 4 warps along N
    const int m0 = blockIdx.y * BM;
    const int n0 = blockIdx.x * BN;

    // ---- cooperative load descriptors ----
    // A: 1024 chunks of 16B (128 rows x 8 chunks). tid -> row0 = tid>>3,
    // chunk c = tid&7. r-th chunk: row += 32r (sA += 4096r, gA += 32r*KD).
    const int lrow = tid >> 3;
    const int lc = tid & 7;
    const uint32_t sA0 = tile_off(lrow, lc);
    const __half* gA0 = g_Xh + (size_t)(m0 + lrow) * KD + lc * 8;
    const __half* gB0 = g_Wh + (size_t)(n0 + lrow) * KD + lc * 8;

    // ---- ldmatrix lane address components ----
    const int r8 = lane & 7;
    const int grp = lane >> 3;
    const int aCh = grp >> 1;        // k 16B-half selector for A
    const int bCh = grp & 1;         // k 16B-half selector for B
    // all fragment row offsets are multiples of 8 -> row&7 == r8 for every tile
    const uint32_t aOff0 = (uint32_t)((wm * 64 + ((grp & 1) << 3) + r8) * 128);
    const uint32_t bOff0 = (uint32_t)((wn * 64 + ((grp >> 1) << 3) + r8) * 128);

    float acc[4][8][4];
#pragma unroll
    for (int i = 0; i < 4; i++)
#pragma unroll
        for (int j = 0; j < 8; j++)
#pragma unroll
            for (int q = 0; q < 4; q++) acc[i][j][q] = 0.0f;

    uint32_t afr[2][4][4], bfr[2][8][2];

#define ISSUE_STAGE(stg, ktile) do {                                          \
        uint32_t a0_ = sbase + (stg) * STAGE_BYTES;                           \
        uint32_t b0_ = a0_ + A_STAGE_BYTES;                                   \
        _Pragma("unroll")                                                     \
        for (int r_ = 0; r_ < 4; r_++)                                        \
            CP_ASYNC16(a0_ + sA0 + r_ * 4096,                                 \
                       gA0 + (size_t)r_ * 32 * KD + (ktile) * BK);            \
        _Pragma("unroll")                                                     \
        for (int r_ = 0; r_ < 8; r_++)                                        \
            CP_ASYNC16(b0_ + sA0 + r_ * 4096,                                 \
                       gB0 + (size_t)r_ * 32 * KD + (ktile) * BK);            \
        CP_COMMIT();                                                          \
    } while (0)

#define LOAD_FRAG(buf, stA_, stB_, ks_) do {                                  \
        uint32_t ca_ = (uint32_t)((((ks_) << 1) | aCh) ^ r8) << 4;            \
        uint32_t cb_ = (uint32_t)((((ks_) << 1) | bCh) ^ r8) << 4;            \
        _Pragma("unroll")                                                     \
        for (int mt_ = 0; mt_ < 4; mt_++)                                     \
            LDSM4(afr[buf][mt_][0], afr[buf][mt_][1],                         \
                  afr[buf][mt_][2], afr[buf][mt_][3],                         \
                  (stA_) + aOff0 + mt_ * 2048 + ca_);                         \
        _Pragma("unroll")                                                     \
        for (int np_ = 0; np_ < 4; np_++)                                     \
            LDSM4(bfr[buf][2 * np_][0], bfr[buf][2 * np_][1],                 \
                  bfr[buf][2 * np_ + 1][0], bfr[buf][2 * np_ + 1][1],         \
                  (stB_) + bOff0 + np_ * 2048 + cb_);                         \
    } while (0)

#define DO_MMA(buf) do {                                                      \
        _Pragma("unroll")                                                     \
        for (int mt_ = 0; mt_ < 4; mt_++)                                     \
            _Pragma("unroll")                                                 \
            for (int nf_ = 0; nf_ < 8; nf_++)                                 \
                MMA16816(acc[mt_][nf_], afr[buf][mt_], bfr[buf][nf_]);        \
    } while (0)

    // ---- prologue: stages 0,1 in flight ----
    ISSUE_STAGE(0, 0);
    ISSUE_STAGE(1, 1);
    CP_WAIT(1);
    __syncthreads();
    LOAD_FRAG(0, sbase, sbase + A_STAGE_BYTES, 0);

    // ---- mainloop ----
#pragma unroll 1
    for (int kt = 0; kt < NT; kt++) {
        const uint32_t stA = sbase + (kt % STAGES) * STAGE_BYTES;
        const uint32_t stB = stA + A_STAGE_BYTES;

        const int nx = kt + 2;
        if (nx < NT) ISSUE_STAGE(nx % STAGES, nx);
        else         CP_COMMIT();

#pragma unroll
        for (int ks = 0; ks < 4; ks++) {
            if (ks < 3) LOAD_FRAG((ks & 1) ^ 1, stA, stB, ks + 1);
            DO_MMA(ks & 1);
        }

        CP_WAIT(1);
        __syncthreads();
        if (kt + 1 < NT) {
            const uint32_t nA = sbase + ((kt + 1) % STAGES) * STAGE_BYTES;
            LOAD_FRAG(0, nA, nA + A_STAGE_BYTES, 0);
        }
    }

    // ---- epilogue ----
    const int qrow = lane >> 2;
    const int qcol = (lane & 3) * 2;
    float2 bias2[8];
#pragma unroll
    for (int nf = 0; nf < 8; nf++) {
        int col = n0 + wn * 64 + nf * 8 + qcol;
        bias2[nf] = *reinterpret_cast<const float2*>(&g_bias[col]);
    }
#pragma unroll
    for (int mt = 0; mt < 4; mt++) {
#pragma unroll
        for (int h = 0; h < 2; h++) {
            int row = m0 + wm * 64 + mt * 16 + qrow + h * 8;
            float* cp = C + (size_t)row * ND + n0 + wn * 64 + qcol;
#pragma unroll
            for (int nf = 0; nf < 8; nf++) {
                float2 v;
                v.x = acc[mt][nf][2 * h + 0] + bias2[nf].x;
                v.y = acc[mt][nf][2 * h + 1] + bias2[nf].y;
                *reinterpret_cast<float2*>(cp + nf * 8) = v;
            }
        }
    }
}

// ---------------------------------------------------------------------------
// Launch. Inputs: x, w_codes, w_absmax, b_codes, b_absmax.
// ---------------------------------------------------------------------------
extern "C" void kernel_launch(void* const* d_in, const int* in_sizes, int n_in,
                              void* d_out, int out_size) {
    const float* x        = (const float*)d_in[0];
    const int*   w_codes  = (const int*)  d_in[1];
    const float* w_absmax = (const float*)d_in[2];
    const int*   b_codes  = (const int*)  d_in[3];
    const float* b_absmax = (const float*)d_in[4];
    float*       out      = (float*)d_out;

    (void)in_sizes; (void)n_in; (void)out_size;

    static bool attr_set = false;
    if (!attr_set) {
        cudaFuncSetAttribute(k_gemm, cudaFuncAttributeMaxDynamicSharedMemorySize,
                             DYN_SMEM);
        attr_set = true;
    }

    k_dequant_w<<<(ND * KD / 16) / 256, 256>>>((const int4*)w_codes, w_absmax);
    k_convert_x<<<(MD * KD / 16) / 256, 256>>>((const float4*)x);
    k_dequant_b<<<ND / 256, 256>>>(b_codes, b_absmax);

    dim3 grid(ND / BN, MD / BM);    // (16, 64)
    k_gemm<<<grid, 256, DYN_SMEM>>>(out);
}

// round 8
// speedup vs baseline: 9.4232x; 1.0145x over previous
#include <cuda_runtime.h>
#include <cuda_fp16.h>
#include <cstdint>
#include <cstddef>

// Problem dims (fixed)
#define MD 8192
#define ND 4096
#define KD 4096

// GEMM tiling
#define BM 128
#define BN 256
#define BK 64                             // 64 fp16 = 128B rows
#define STAGES 4
#define NT (KD / BK)                      // 64 k-iterations per tile
#define NTILES ((MD / BM) * (ND / BN))    // 64 * 16 = 1024
#define PGRID 148                         // persistent CTAs (1/SM)
#define A_STAGE_BYTES (BM * 128)          // 16 KB
#define B_STAGE_BYTES (BN * 128)          // 32 KB
#define STAGE_BYTES (A_STAGE_BYTES + B_STAGE_BYTES)   // 48 KB
#define DYN_SMEM (STAGES * STAGE_BYTES)   // 196608

static __constant__ float c_nf4[16] = {
    -1.0f, -0.6961928009986877f, -0.5250730514526367f, -0.39491748809814453f,
    -0.28444138169288635f, -0.18477343022823334f, -0.09105003625154495f, 0.0f,
    0.07958029955625534f, 0.16093020141124725f, 0.24611230194568634f,
    0.33791524171829224f, 0.44070982933044434f, 0.5626170039176941f,
    0.6848514676094055f, 1.0f
};

__device__ __half g_Wh[(size_t)ND * KD];   // 32 MB fp16 weights
__device__ __half g_Xh[(size_t)MD * KD];   // 64 MB fp16 activations
__device__ float  g_bias[ND];

union H8 {
    uint4 u;
    __half2 h[4];
};

// ---------------------------------------------------------------------------
// Prep kernels — 32 elements/thread (MLP=8)
// ---------------------------------------------------------------------------
__global__ void k_dequant_w(const int4* __restrict__ codes,
                            const float* __restrict__ absmax) {
    int i = blockIdx.x * blockDim.x + threadIdx.x;     // [0, ND*KD/32)
    float am = __ldg(&absmax[i >> 1]);                 // 32 codes = half a block
#pragma unroll
    for (int h = 0; h < 4; h++) {
        int4 c0 = codes[8 * i + 2 * h + 0];
        int4 c1 = codes[8 * i + 2 * h + 1];
        H8 v;
        v.h[0] = __floats2half2_rn(c_nf4[c0.x] * am, c_nf4[c0.y] * am);
        v.h[1] = __floats2half2_rn(c_nf4[c0.z] * am, c_nf4[c0.w] * am);
        v.h[2] = __floats2half2_rn(c_nf4[c1.x] * am, c_nf4[c1.y] * am);
        v.h[3] = __floats2half2_rn(c_nf4[c1.z] * am, c_nf4[c1.w] * am);
        reinterpret_cast<uint4*>(g_Wh)[4 * i + h] = v.u;
    }
}

__global__ void k_convert_x(const float4* __restrict__ x) {
    int i = blockIdx.x * blockDim.x + threadIdx.x;     // [0, MD*KD/32)
#pragma unroll
    for (int h = 0; h < 4; h++) {
        float4 a = x[8 * i + 2 * h + 0];
        float4 b = x[8 * i + 2 * h + 1];
        H8 v;
        v.h[0] = __floats2half2_rn(a.x, a.y);
        v.h[1] = __floats2half2_rn(a.z, a.w);
        v.h[2] = __floats2half2_rn(b.x, b.y);
        v.h[3] = __floats2half2_rn(b.z, b.w);
        reinterpret_cast<uint4*>(g_Xh)[4 * i + h] = v.u;
    }
}

__global__ void k_dequant_b(const int* __restrict__ codes,
                            const float* __restrict__ absmax) {
    int i = blockIdx.x * blockDim.x + threadIdx.x;
    if (i < ND) g_bias[i] = c_nf4[codes[i]] * absmax[i >> 6];
}

// ---------------------------------------------------------------------------
// PTX helpers (baseline sm_80+)
// ---------------------------------------------------------------------------
__device__ __forceinline__ uint32_t smem_u32(const void* p) {
    uint32_t a;
    asm("{ .reg .u64 t; cvta.to.shared.u64 t, %1; cvt.u32.u64 %0, t; }"
        : "=r"(a) : "l"(p));
    return a;
}

#define CP_ASYNC16(saddr, gptr) \
    asm volatile("cp.async.cg.shared.global [%0], [%1], 16;" \
                 :: "r"(saddr), "l"(gptr))

#define CP_COMMIT() asm volatile("cp.async.commit_group;" ::: "memory")
#define CP_WAIT(n)  asm volatile("cp.async.wait_group %0;" :: "n"(n) : "memory")

#define LDSM4(r0, r1, r2, r3, addr) \
    asm volatile("ldmatrix.sync.aligned.m8n8.x4.shared.b16 {%0,%1,%2,%3}, [%4];" \
                 : "=r"(r0), "=r"(r1), "=r"(r2), "=r"(r3) : "r"(addr))

#define MMA16816(d, a, b) \
    asm volatile("mma.sync.aligned.m16n8k16.row.col.f32.f16.f16.f32 " \
                 "{%0,%1,%2,%3}, {%4,%5,%6,%7}, {%8,%9}, {%0,%1,%2,%3};" \
                 : "+f"((d)[0]), "+f"((d)[1]), "+f"((d)[2]), "+f"((d)[3]) \
                 : "r"((a)[0]), "r"((a)[1]), "r"((a)[2]), "r"((a)[3]), \
                   "r"((b)[0]), "r"((b)[1]))

// 128B-row SW128 swizzle: 16B chunk c (0..7) -> c ^ (row & 7).
__device__ __forceinline__ uint32_t tile_off(int row, int c) {
    return (uint32_t)(row * 128 + ((c ^ (row & 7)) << 4));
}

// ---------------------------------------------------------------------------
// Persistent GEMM: C = Xh * Wh^T + bias. 148 CTAs, each loops over tiles
// with a never-draining 4-stage cp.async pipeline.
// ---------------------------------------------------------------------------
__global__ __launch_bounds__(256)
void k_gemm(float* __restrict__ C) {
    extern __shared__ char dynsmem[];
    const uint32_t sbase = smem_u32(dynsmem);

    const int tid = threadIdx.x;
    const int wid = tid >> 5;
    const int lane = tid & 31;
    const int wm = wid & 1;
    const int wn = wid >> 1;
    const int cta = blockIdx.x;

    // cooperative-load lane geometry (row lrow, 16B chunk lc of 8)
    const int lrow = tid >> 3;
    const int lc = tid & 7;
    const uint32_t sA0 = tile_off(lrow, lc);

    // ldmatrix lane address components
    const int r8 = lane & 7;
    const int grp = lane >> 3;
    const int aCh = grp >> 1;
    const int bCh = grp & 1;
    const uint32_t aOff0 = (uint32_t)((wm * 64 + ((grp & 1) << 3) + r8) * 128);
    const uint32_t bOff0 = (uint32_t)((wn * 64 + ((grp >> 1) << 3) + r8) * 128);

    float acc[4][8][4];
#pragma unroll
    for (int i = 0; i < 4; i++)
#pragma unroll
        for (int j = 0; j < 8; j++)
#pragma unroll
            for (int q = 0; q < 4; q++) acc[i][j][q] = 0.0f;

    uint32_t afr[2][4][4], bfr[2][8][2];

    // Issue one stage for global iteration g (tile w = g/NT of this CTA).
    // Always commits (keeps group accounting uniform).
#define ISSUE_G(g) do {                                                       \
        int w_ = (g) >> 6;                                                    \
        int tile_ = cta + w_ * PGRID;                                         \
        if (tile_ < NTILES) {                                                 \
            int k_ = (g) & (NT - 1);                                          \
            int m0_ = (tile_ >> 4) * BM;                                      \
            int n0_ = (tile_ & 15) * BN;                                      \
            const __half* gA_ = g_Xh + (size_t)(m0_ + lrow) * KD              \
                                + lc * 8 + k_ * BK;                           \
            const __half* gB_ = g_Wh + (size_t)(n0_ + lrow) * KD              \
                                + lc * 8 + k_ * BK;                           \
            uint32_t a0_ = sbase + ((g) & 3) * STAGE_BYTES;                   \
            uint32_t b0_ = a0_ + A_STAGE_BYTES;                               \
            _Pragma("unroll")                                                 \
            for (int r_ = 0; r_ < 4; r_++)                                    \
                CP_ASYNC16(a0_ + sA0 + r_ * 4096,                             \
                           gA_ + (size_t)r_ * 32 * KD);                       \
            _Pragma("unroll")                                                 \
            for (int r_ = 0; r_ < 8; r_++)                                    \
                CP_ASYNC16(b0_ + sA0 + r_ * 4096,                             \
                           gB_ + (size_t)r_ * 32 * KD);                       \
        }                                                                     \
        CP_COMMIT();                                                          \
    } while (0)

#define LOAD_FRAG(buf, stA_, stB_, ks_) do {                                  \
        uint32_t ca_ = (uint32_t)((((ks_) << 1) | aCh) ^ r8) << 4;            \
        uint32_t cb_ = (uint32_t)((((ks_) << 1) | bCh) ^ r8) << 4;            \
        _Pragma("unroll")                                                     \
        for (int mt_ = 0; mt_ < 4; mt_++)                                     \
            LDSM4(afr[buf][mt_][0], afr[buf][mt_][1],                         \
                  afr[buf][mt_][2], afr[buf][mt_][3],                         \
                  (stA_) + aOff0 + mt_ * 2048 + ca_);                         \
        _Pragma("unroll")                                                     \
        for (int np_ = 0; np_ < 4; np_++)                                     \
            LDSM4(bfr[buf][2 * np_][0], bfr[buf][2 * np_][1],                 \
                  bfr[buf][2 * np_ + 1][0], bfr[buf][2 * np_ + 1][1],         \
                  (stB_) + bOff0 + np_ * 2048 + cb_);                         \
    } while (0)

#define DO_MMA(buf) do {                                                      \
        _Pragma("unroll")                                                     \
        for (int mt_ = 0; mt_ < 4; mt_++)                                     \
            _Pragma("unroll")                                                 \
            for (int nf_ = 0; nf_ < 8; nf_++)                                 \
                MMA16816(acc[mt_][nf_], afr[buf][mt_], bfr[buf][nf_]);        \
    } while (0)

    if (cta >= NTILES) return;   // (never true here, but safe)

    // ---- prologue: stages for g=0,1,2 ----
    ISSUE_G(0);
    ISSUE_G(1);
    ISSUE_G(2);
    CP_WAIT(2);
    __syncthreads();
    LOAD_FRAG(0, sbase, sbase + A_STAGE_BYTES, 0);

    int gg = 0;
    for (int tile = cta; tile < NTILES; tile += PGRID) {
#pragma unroll 1
        for (int kt = 0; kt < NT; kt++, gg++) {
            const uint32_t stA = sbase + (gg & 3) * STAGE_BYTES;
            const uint32_t stB = stA + A_STAGE_BYTES;

            ISSUE_G(gg + 3);

#pragma unroll
            for (int ks = 0; ks < 4; ks++) {
                if (ks < 3) LOAD_FRAG((ks & 1) ^ 1, stA, stB, ks + 1);
                DO_MMA(ks & 1);
            }

            CP_WAIT(2);
            __syncthreads();
            const uint32_t nA = sbase + ((gg + 1) & 3) * STAGE_BYTES;
            LOAD_FRAG(0, nA, nA + A_STAGE_BYTES, 0);
        }

        // ---- epilogue for this tile (prefetch for next tile already in flight)
        {
            const int m0 = (tile >> 4) * BM;
            const int n0 = (tile & 15) * BN;
            const int qrow = lane >> 2;
            const int qcol = (lane & 3) * 2;
            float2 bias2[8];
#pragma unroll
            for (int nf = 0; nf < 8; nf++) {
                int col = n0 + wn * 64 + nf * 8 + qcol;
                bias2[nf] = *reinterpret_cast<const float2*>(&g_bias[col]);
            }
#pragma unroll
            for (int mt = 0; mt < 4; mt++) {
#pragma unroll
                for (int h = 0; h < 2; h++) {
                    int row = m0 + wm * 64 + mt * 16 + qrow + h * 8;
                    float* cp = C + (size_t)row * ND + n0 + wn * 64 + qcol;
#pragma unroll
                    for (int nf = 0; nf < 8; nf++) {
                        float2 v;
                        v.x = acc[mt][nf][2 * h + 0] + bias2[nf].x;
                        v.y = acc[mt][nf][2 * h + 1] + bias2[nf].y;
                        *reinterpret_cast<float2*>(cp + nf * 8) = v;
                    }
                }
            }
        }
        // reset accumulators for the next tile
#pragma unroll
        for (int i = 0; i < 4; i++)
#pragma unroll
            for (int j = 0; j < 8; j++)
#pragma unroll
                for (int q = 0; q < 4; q++) acc[i][j][q] = 0.0f;
    }
}

// ---------------------------------------------------------------------------
// Launch. Inputs: x, w_codes, w_absmax, b_codes, b_absmax.
// ---------------------------------------------------------------------------
extern "C" void kernel_launch(void* const* d_in, const int* in_sizes, int n_in,
                              void* d_out, int out_size) {
    const float* x        = (const float*)d_in[0];
    const int*   w_codes  = (const int*)  d_in[1];
    const float* w_absmax = (const float*)d_in[2];
    const int*   b_codes  = (const int*)  d_in[3];
    const float* b_absmax = (const float*)d_in[4];
    float*       out      = (float*)d_out;

    (void)in_sizes; (void)n_in; (void)out_size;

    static bool attr_set = false;
    if (!attr_set) {
        cudaFuncSetAttribute(k_gemm, cudaFuncAttributeMaxDynamicSharedMemorySize,
                             DYN_SMEM);
        attr_set = true;
    }

    k_dequant_w<<<(ND * KD / 32) / 256, 256>>>((const int4*)w_codes, w_absmax);
    k_convert_x<<<(MD * KD / 32) / 256, 256>>>((const float4*)x);
    k_dequant_b<<<ND / 256, 256>>>(b_codes, b_absmax);

    k_gemm<<<PGRID, 256, DYN_SMEM>>>(out);
}